// round 6
// baseline (speedup 1.0000x reference)
#include <cuda_runtime.h>
#include <cstdint>

#define Mm 32768   // B*N points

// ---------------- static device scratch ----------------
__device__ float g_qg[Mm * 64];   // x @ (wq@g1)
__device__ float g_kg[Mm * 64];   // x @ (wk@g1)
__device__ float g_v [Mm * 64];   // x @ wv
__device__ float g_Wd2g1[4096];   // d2 @ g1
__device__ float g_Wqg1[4096];    // wq @ g1
__device__ float g_Wkg1[4096];    // wk @ g1
__device__ float g_cvec[64];      // d2b @ g1 + g1b

// ---------------- f32x2 packed-FMA helpers ----------------
__device__ __forceinline__ unsigned long long pack2(float x, float y) {
    unsigned long long r; asm("mov.b64 %0, {%1, %2};" : "=l"(r) : "f"(x), "f"(y)); return r;
}
__device__ __forceinline__ void fma2(unsigned long long& d, unsigned long long a, unsigned long long b) {
    asm("fma.rn.f32x2 %0, %1, %2, %0;" : "+l"(d) : "l"(a), "l"(b));
}
__device__ __forceinline__ float2 unpk(unsigned long long v) {
    float x, y; asm("mov.b64 {%0, %1}, %2;" : "=f"(x), "=f"(y) : "l"(v)); return make_float2(x, y);
}

// ---------------- 4x4-tile gemm (k0/k1) ----------------
__device__ __forceinline__ void rank1(float a0, float a1, float a2, float a3,
                                      ulonglong2 b, unsigned long long acc[4][2]) {
    unsigned long long t;
    t = pack2(a0, a0); fma2(acc[0][0], t, b.x); fma2(acc[0][1], t, b.y);
    t = pack2(a1, a1); fma2(acc[1][0], t, b.x); fma2(acc[1][1], t, b.y);
    t = pack2(a2, a2); fma2(acc[2][0], t, b.x); fma2(acc[2][1], t, b.y);
    t = pack2(a3, a3); fma2(acc[3][0], t, b.x); fma2(acc[3][1], t, b.y);
}
__device__ __forceinline__ void gemm64(const float* As, const float* Ws,
                                       int r0, int c0, unsigned long long acc[4][2]) {
#pragma unroll
    for (int i = 0; i < 4; i++) { acc[i][0] = 0ULL; acc[i][1] = 0ULL; }
#pragma unroll
    for (int k4 = 0; k4 < 16; ++k4) {
        float4 a0 = *reinterpret_cast<const float4*>(As + (r0 + 0) * 68 + k4 * 4);
        float4 a1 = *reinterpret_cast<const float4*>(As + (r0 + 1) * 68 + k4 * 4);
        float4 a2 = *reinterpret_cast<const float4*>(As + (r0 + 2) * 68 + k4 * 4);
        float4 a3 = *reinterpret_cast<const float4*>(As + (r0 + 3) * 68 + k4 * 4);
        ulonglong2 b0 = *reinterpret_cast<const ulonglong2*>(Ws + (k4 * 4 + 0) * 68 + c0);
        ulonglong2 b1 = *reinterpret_cast<const ulonglong2*>(Ws + (k4 * 4 + 1) * 68 + c0);
        ulonglong2 b2 = *reinterpret_cast<const ulonglong2*>(Ws + (k4 * 4 + 2) * 68 + c0);
        ulonglong2 b3 = *reinterpret_cast<const ulonglong2*>(Ws + (k4 * 4 + 3) * 68 + c0);
        rank1(a0.x, a1.x, a2.x, a3.x, b0, acc);
        rank1(a0.y, a1.y, a2.y, a3.y, b1, acc);
        rank1(a0.z, a1.z, a2.z, a3.z, b2, acc);
        rank1(a0.w, a1.w, a2.w, a3.w, b3, acc);
    }
}
__device__ __forceinline__ void loadW(float* dst, const float* __restrict__ src, int tid) {
#pragma unroll
    for (int e = tid; e < 1024; e += 256) {
        int row = e >> 4, c4 = e & 15;
        float4 v = *reinterpret_cast<const float4*>(src + row * 64 + c4 * 4);
        *reinterpret_cast<float4*>(dst + row * 68 + c4 * 4) = v;
    }
}

// =========================================================================
// k0: weight products  Wd2g1 = d2@g1, Wqg1 = wq@g1, Wkg1 = wk@g1,
//     cvec = d2b@g1 + g1b.
// =========================================================================
__global__ __launch_bounds__(256)
void k0_prep(const float* __restrict__ d2w, const float* __restrict__ g1w,
             const float* __restrict__ wq, const float* __restrict__ wk,
             const float* __restrict__ d2b, const float* __restrict__ g1b) {
    __shared__ float As[64 * 68];
    __shared__ float Bs[64 * 68];
    const int tid = threadIdx.x, m = blockIdx.x;
    const float* A = (m == 0) ? d2w : (m == 1) ? wq : wk;
    loadW(As, A, tid);
    loadW(Bs, g1w, tid);
    __syncthreads();
    const int r0 = (tid >> 4) * 4, c0 = (tid & 15) * 4;
    unsigned long long acc[4][2];
    gemm64(As, Bs, r0, c0, acc);
    float* dst = (m == 0) ? g_Wd2g1 : (m == 1) ? g_Wqg1 : g_Wkg1;
#pragma unroll
    for (int i = 0; i < 4; i++) {
        float2 u0 = unpk(acc[i][0]), u1 = unpk(acc[i][1]);
        *reinterpret_cast<float4*>(dst + (r0 + i) * 64 + c0) = make_float4(u0.x, u0.y, u1.x, u1.y);
    }
    if (m == 0 && tid < 64) {
        float c = g1b[tid];
#pragma unroll 8
        for (int k = 0; k < 64; k++) c = fmaf(__ldg(&d2b[k]), Bs[k * 68 + tid], c);
        g_cvec[tid] = c;
    }
}

// =========================================================================
// k1: x = features@fc1+b ; qg = x@Wqg1 ; kg = x@Wkg1 ; v = x@wv
// =========================================================================
__global__ __launch_bounds__(256)
void k1_proj(const float* __restrict__ features,
             const float* __restrict__ fc1w, const float* __restrict__ fc1b,
             const float* __restrict__ wv) {
    __shared__ float Fs[64 * 68];
    __shared__ float Ws[64 * 68];
    const int tid = threadIdx.x;
    const int m0 = blockIdx.x * 64;
    const int r0 = (tid >> 4) * 4, c0 = (tid & 15) * 4;

#pragma unroll
    for (int e = tid; e < 1024; e += 256) {
        int row = e >> 4, c4 = e & 15;
        float4 v = *reinterpret_cast<const float4*>(features + (m0 + row) * 64 + c4 * 4);
        *reinterpret_cast<float4*>(Fs + row * 68 + c4 * 4) = v;
    }
    loadW(Ws, fc1w, tid);
    __syncthreads();

    unsigned long long acc[4][2];
    gemm64(Fs, Ws, r0, c0, acc);
    __syncthreads();
#pragma unroll
    for (int i = 0; i < 4; i++) {
        float2 u0 = unpk(acc[i][0]), u1 = unpk(acc[i][1]);
        Fs[(r0 + i) * 68 + c0 + 0] = u0.x + __ldg(&fc1b[c0 + 0]);
        Fs[(r0 + i) * 68 + c0 + 1] = u0.y + __ldg(&fc1b[c0 + 1]);
        Fs[(r0 + i) * 68 + c0 + 2] = u1.x + __ldg(&fc1b[c0 + 2]);
        Fs[(r0 + i) * 68 + c0 + 3] = u1.y + __ldg(&fc1b[c0 + 3]);
    }
    loadW(Ws, (const float*)g_Wqg1, tid);
    __syncthreads();
    gemm64(Fs, Ws, r0, c0, acc);
#pragma unroll
    for (int i = 0; i < 4; i++) {
        float2 u0 = unpk(acc[i][0]), u1 = unpk(acc[i][1]);
        *reinterpret_cast<float4*>(g_qg + (m0 + r0 + i) * 64 + c0) = make_float4(u0.x, u0.y, u1.x, u1.y);
    }
    __syncthreads();
    loadW(Ws, (const float*)g_Wkg1, tid);
    __syncthreads();
    gemm64(Fs, Ws, r0, c0, acc);
#pragma unroll
    for (int i = 0; i < 4; i++) {
        float2 u0 = unpk(acc[i][0]), u1 = unpk(acc[i][1]);
        *reinterpret_cast<float4*>(g_kg + (m0 + r0 + i) * 64 + c0) = make_float4(u0.x, u0.y, u1.x, u1.y);
    }
    __syncthreads();
    loadW(Ws, wv, tid);
    __syncthreads();
    gemm64(Fs, Ws, r0, c0, acc);
#pragma unroll
    for (int i = 0; i < 4; i++) {
        float2 u0 = unpk(acc[i][0]), u1 = unpk(acc[i][1]);
        *reinterpret_cast<float4*>(g_v + (m0 + r0 + i) * 64 + c0) = make_float4(u0.x, u0.y, u1.x, u1.y);
    }
}

// =========================================================================
// k2: block = 256 thr = 4 groups x 64 thr; group = 64 rows (4 pts x 16 nbrs).
// 8x8 register tiles. Activation buffers stride-68 (NO xor swizzle):
// inner-loop A reads = LDS [ptr + imm], zero address math. W rows padded
// col + 4*(col>=32) -> gemm-side smem accesses conflict-free.
// =========================================================================
__device__ __forceinline__ void gemmT(const float* __restrict__ Tb,
                                      const float* __restrict__ W,
                                      int tr, int tcoff, unsigned long long acc[8][4]) {
    const float4* ap0 = reinterpret_cast<const float4*>(Tb + (tr +  0) * 68);
    const float4* ap1 = reinterpret_cast<const float4*>(Tb + (tr +  8) * 68);
    const float4* ap2 = reinterpret_cast<const float4*>(Tb + (tr + 16) * 68);
    const float4* ap3 = reinterpret_cast<const float4*>(Tb + (tr + 24) * 68);
    const float4* ap4 = reinterpret_cast<const float4*>(Tb + (tr + 32) * 68);
    const float4* ap5 = reinterpret_cast<const float4*>(Tb + (tr + 40) * 68);
    const float4* ap6 = reinterpret_cast<const float4*>(Tb + (tr + 48) * 68);
    const float4* ap7 = reinterpret_cast<const float4*>(Tb + (tr + 56) * 68);
    const ulonglong2* wp = reinterpret_cast<const ulonglong2*>(W + tcoff);
#pragma unroll
    for (int i = 0; i < 8; i++) { acc[i][0] = acc[i][1] = acc[i][2] = acc[i][3] = 0ULL; }
#pragma unroll
    for (int k4 = 0; k4 < 16; k4++) {
        float4 Av[8];
        Av[0] = ap0[k4]; Av[1] = ap1[k4]; Av[2] = ap2[k4]; Av[3] = ap3[k4];
        Av[4] = ap4[k4]; Av[5] = ap5[k4]; Av[6] = ap6[k4]; Av[7] = ap7[k4];
#pragma unroll
        for (int kk = 0; kk < 4; kk++) {
            ulonglong2 b0 = wp[(k4 * 4 + kk) * 17];
            ulonglong2 b1 = wp[(k4 * 4 + kk) * 17 + 1];
#pragma unroll
            for (int i = 0; i < 8; i++) {
                float a = (kk == 0) ? Av[i].x : (kk == 1) ? Av[i].y : (kk == 2) ? Av[i].z : Av[i].w;
                unsigned long long t = pack2(a, a);
                fma2(acc[i][0], t, b0.x); fma2(acc[i][1], t, b0.y);
                fma2(acc[i][2], t, b1.x); fma2(acc[i][3], t, b1.y);
            }
        }
    }
}

__global__ __launch_bounds__(256)
void k2_main(const float* __restrict__ xyz, const float* __restrict__ features,
             const int* __restrict__ knn,
             const float* __restrict__ d1w, const float* __restrict__ d1b,
             const float* __restrict__ d2w, const float* __restrict__ d2b,
             const float* __restrict__ g2w, const float* __restrict__ g2b,
             const float* __restrict__ fc2w, const float* __restrict__ fc2b,
             float* __restrict__ outRes, float* __restrict__ outAttn) {
    extern __shared__ float sm[];
    float* Wd2   = sm;                     // 4352
    float* Wg1p  = sm + 4352;              // 4352
    float* Wg2   = sm + 8704;              // 4352
    const int tid = threadIdx.x;
    const int g = tid >> 6, l = tid & 63;
    const int tc = l & 7, tr = l >> 3;
    float* Tb    = sm + 13056 + g * 4352;  // 64 rows x stride 68
    float* vpS   = sm + 30464 + g * 4352;  // 64 rows x stride 68
    float* qgS   = sm + 47872;             // 1024
    float* resS  = sm + 48896;             // 1024
    int*   growsS = (int*)(sm + 49920);    // 256
    float* d1S   = sm + 50176;             // 192
    float* d1bS  = sm + 50368;
    float* d2bS  = sm + 50432;
    float* cvecS = sm + 50496;
    float* g2bS  = sm + 50560;             // end 50624 floats = 202496 B
    const int pbase = blockIdx.x * 16;

    // ---- setup ----
    for (int e = tid; e < 4096; e += 256) { int k = e >> 6, c = e & 63; Wd2 [k * 68 + c + ((c >> 5) << 2)] = d2w[e]; }
    for (int e = tid; e < 4096; e += 256) { int k = e >> 6, c = e & 63; Wg1p[k * 68 + c + ((c >> 5) << 2)] = g_Wd2g1[e]; }
    for (int e = tid; e < 4096; e += 256) { int k = e >> 6, c = e & 63; Wg2 [k * 68 + c + ((c >> 5) << 2)] = g2w[e]; }
    if (tid < 192) d1S[tid] = d1w[tid];
    if (tid < 64) { d1bS[tid] = d1b[tid]; d2bS[tid] = d2b[tid]; cvecS[tid] = g_cvec[tid]; g2bS[tid] = g2b[tid]; }
    for (int e = tid; e < 1024; e += 256) qgS[e] = g_qg[(pbase + (e >> 6)) * 64 + (e & 63)];

    const int pi_st = pbase + g * 4 + (l >> 4);
    const int grow_st = ((pi_st >> 13) << 13) | knn[pi_st * 16 + (l & 15)];
    growsS[g * 64 + l] = grow_st;
    const float rx = xyz[pi_st * 3 + 0] - xyz[grow_st * 3 + 0];
    const float ry = xyz[pi_st * 3 + 1] - xyz[grow_st * 3 + 1];
    const float rz = xyz[pi_st * 3 + 2] - xyz[grow_st * 3 + 2];
    __syncthreads();

    // ---- stage T = relu(rel@d1 + d1b) ----
    {
        const int r = l;
#pragma unroll
        for (int c4 = 0; c4 < 16; c4++) {
            float v[4];
#pragma unroll
            for (int u = 0; u < 4; u++) {
                int f = c4 * 4 + u;
                v[u] = fmaxf(fmaf(rx, d1S[f], fmaf(ry, d1S[64 + f], fmaf(rz, d1S[128 + f], d1bS[f]))), 0.f);
            }
            *reinterpret_cast<float4*>(Tb + r * 68 + c4 * 4) = make_float4(v[0], v[1], v[2], v[3]);
        }
    }
    __syncthreads();

    const int tcoff = tc * 8 + ((tc >> 2) << 2);
    const int c0 = tc * 8;
    unsigned long long acc[8][4];

    // ---- GEMM1: pos = T@d2 (+d2b); vp = v_gather + pos -> vpS ----
    gemmT(Tb, Wd2, tr, tcoff, acc);
#pragma unroll
    for (int i = 0; i < 8; i++) {
        int r = tr + 8 * i;
        int grow = growsS[g * 64 + r];
        float4 v0 = __ldg(reinterpret_cast<const float4*>(g_v + (size_t)grow * 64 + c0));
        float4 v1 = __ldg(reinterpret_cast<const float4*>(g_v + (size_t)grow * 64 + c0 + 4));
        float2 pA = unpk(acc[i][0]), pB = unpk(acc[i][1]), pC = unpk(acc[i][2]), pD = unpk(acc[i][3]);
        float4 w0 = make_float4(v0.x + pA.x + d2bS[c0 + 0], v0.y + pA.y + d2bS[c0 + 1],
                                v0.z + pB.x + d2bS[c0 + 2], v0.w + pB.y + d2bS[c0 + 3]);
        float4 w1 = make_float4(v1.x + pC.x + d2bS[c0 + 4], v1.y + pC.y + d2bS[c0 + 5],
                                v1.z + pD.x + d2bS[c0 + 6], v1.w + pD.y + d2bS[c0 + 7]);
        *reinterpret_cast<float4*>(vpS + r * 68 + c0)     = w0;
        *reinterpret_cast<float4*>(vpS + r * 68 + c0 + 4) = w1;
    }

    // ---- GEMM2: Tg = T@(d2@g1); a1 = relu(Tg + qg - kg + cvec) ----
    gemmT(Tb, Wg1p, tr, tcoff, acc);
#pragma unroll
    for (int i = 0; i < 8; i++) {
        int r = tr + 8 * i;
        int grow = growsS[g * 64 + r];
        int lp = g * 4 + (r >> 4);
        float4 k0v = __ldg(reinterpret_cast<const float4*>(g_kg + (size_t)grow * 64 + c0));
        float4 k1v = __ldg(reinterpret_cast<const float4*>(g_kg + (size_t)grow * 64 + c0 + 4));
        float4 q0 = *reinterpret_cast<const float4*>(qgS + lp * 64 + c0);
        float4 q1 = *reinterpret_cast<const float4*>(qgS + lp * 64 + c0 + 4);
        float2 aA = unpk(acc[i][0]), aB = unpk(acc[i][1]), aC = unpk(acc[i][2]), aD = unpk(acc[i][3]);
        float a0 = fmaxf(aA.x + q0.x - k0v.x + cvecS[c0 + 0], 0.f);
        float a1 = fmaxf(aA.y + q0.y - k0v.y + cvecS[c0 + 1], 0.f);
        float a2 = fmaxf(aB.x + q0.z - k0v.z + cvecS[c0 + 2], 0.f);
        float a3 = fmaxf(aB.y + q0.w - k0v.w + cvecS[c0 + 3], 0.f);
        float a4 = fmaxf(aC.x + q1.x - k1v.x + cvecS[c0 + 4], 0.f);
        float a5 = fmaxf(aC.y + q1.y - k1v.y + cvecS[c0 + 5], 0.f);
        float a6 = fmaxf(aD.x + q1.z - k1v.z + cvecS[c0 + 6], 0.f);
        float a7 = fmaxf(aD.y + q1.w - k1v.w + cvecS[c0 + 7], 0.f);
        acc[i][0] = pack2(a0, a1); acc[i][1] = pack2(a2, a3);
        acc[i][2] = pack2(a4, a5); acc[i][3] = pack2(a6, a7);
    }
    __syncthreads();   // all GEMM1/2 reads of Tb done
#pragma unroll
    for (int i = 0; i < 8; i++) {
        int r = tr + 8 * i;
        *reinterpret_cast<ulonglong2*>(Tb + r * 68 + c0)     = make_ulonglong2(acc[i][0], acc[i][1]);
        *reinterpret_cast<ulonglong2*>(Tb + r * 68 + c0 + 4) = make_ulonglong2(acc[i][2], acc[i][3]);
    }
    __syncthreads();

    // ---- GEMM3: logits = a1@g2 + g2b ----
    gemmT(Tb, Wg2, tr, tcoff, acc);
#pragma unroll
    for (int i = 0; i < 8; i++) {
        float2 aA = unpk(acc[i][0]), aB = unpk(acc[i][1]), aC = unpk(acc[i][2]), aD = unpk(acc[i][3]);
        acc[i][0] = pack2(aA.x + g2bS[c0 + 0], aA.y + g2bS[c0 + 1]);
        acc[i][1] = pack2(aB.x + g2bS[c0 + 2], aB.y + g2bS[c0 + 3]);
        acc[i][2] = pack2(aC.x + g2bS[c0 + 4], aC.y + g2bS[c0 + 5]);
        acc[i][3] = pack2(aD.x + g2bS[c0 + 6], aD.y + g2bS[c0 + 7]);
    }
    __syncthreads();   // all GEMM3 reads done
#pragma unroll
    for (int i = 0; i < 8; i++) {
        int r = tr + 8 * i;
        *reinterpret_cast<ulonglong2*>(Tb + r * 68 + c0)     = make_ulonglong2(acc[i][0], acc[i][1]);
        *reinterpret_cast<ulonglong2*>(Tb + r * 68 + c0 + 4) = make_ulonglong2(acc[i][2], acc[i][3]);
    }
    __syncthreads();

    // ---- softmax over neighbors (axis j) per (point, channel) + res ----
    {
        const int f = l;
#pragma unroll
        for (int p = 0; p < 4; p++) {
            const int pi = pbase + g * 4 + p;
            float z[16], m = -3.402823e38f;
#pragma unroll
            for (int j = 0; j < 16; j++) {
                z[j] = Tb[(p * 16 + j) * 68 + f];
                m = fmaxf(m, z[j]);
            }
            float s = 0.f;
#pragma unroll
            for (int j = 0; j < 16; j++) { float e = __expf((z[j] - m) * 0.125f); z[j] = e; s += e; }
            float inv = 1.f / s, racc = 0.f;
#pragma unroll
            for (int j = 0; j < 16; j++) {
                float a = z[j] * inv;
                outAttn[((size_t)pi * 16 + j) * 64 + f] = a;
                racc = fmaf(a, vpS[(p * 16 + j) * 68 + f], racc);
            }
            resS[(g * 4 + p) * 64 + f] = racc;
        }
    }
    __syncthreads();

    // ---- out = res@fc2 + fc2b + features ----
    {
        const int f = l, lpb = g * 4;
        float o0 = fc2b[f] + features[(size_t)(pbase + lpb + 0) * 64 + f];
        float o1 = fc2b[f] + features[(size_t)(pbase + lpb + 1) * 64 + f];
        float o2 = fc2b[f] + features[(size_t)(pbase + lpb + 2) * 64 + f];
        float o3 = fc2b[f] + features[(size_t)(pbase + lpb + 3) * 64 + f];
#pragma unroll 8
        for (int i = 0; i < 64; i++) {
            float w = __ldg(fc2w + i * 64 + f);
            o0 = fmaf(resS[(lpb + 0) * 64 + i], w, o0);
            o1 = fmaf(resS[(lpb + 1) * 64 + i], w, o1);
            o2 = fmaf(resS[(lpb + 2) * 64 + i], w, o2);
            o3 = fmaf(resS[(lpb + 3) * 64 + i], w, o3);
        }
        outRes[(size_t)(pbase + lpb + 0) * 64 + f] = o0;
        outRes[(size_t)(pbase + lpb + 1) * 64 + f] = o1;
        outRes[(size_t)(pbase + lpb + 2) * 64 + f] = o2;
        outRes[(size_t)(pbase + lpb + 3) * 64 + f] = o3;
    }
}

// =========================================================================
extern "C" void kernel_launch(void* const* d_in, const int* in_sizes, int n_in,
                              void* d_out, int out_size) {
    const float* xyz      = (const float*)d_in[0];
    const float* features = (const float*)d_in[1];
    const int*   knn      = (const int*)d_in[2];
    const float* fc1w = (const float*)d_in[3];
    const float* fc1b = (const float*)d_in[4];
    const float* fc2w = (const float*)d_in[5];
    const float* fc2b = (const float*)d_in[6];
    const float* d1w  = (const float*)d_in[7];
    const float* d1b  = (const float*)d_in[8];
    const float* d2w  = (const float*)d_in[9];
    const float* d2b  = (const float*)d_in[10];
    const float* g1w  = (const float*)d_in[11];
    const float* g1b  = (const float*)d_in[12];
    const float* g2w  = (const float*)d_in[13];
    const float* g2b  = (const float*)d_in[14];
    const float* wq   = (const float*)d_in[15];
    const float* wk   = (const float*)d_in[16];
    const float* wv   = (const float*)d_in[17];

    float* outRes  = (float*)d_out;
    float* outAttn = outRes + (size_t)Mm * 64;   // tuple order: (res, attn)

    const int smem2 = 50624 * 4;   // 202496 B
    cudaFuncSetAttribute(k2_main, cudaFuncAttributeMaxDynamicSharedMemorySize, smem2);

    k0_prep<<<3, 256>>>(d2w, g1w, wq, wk, d2b, g1b);
    k1_proj<<<Mm / 64, 256>>>(features, fc1w, fc1b, wv);
    k2_main<<<Mm / 16, 256, smem2>>>(xyz, features, knn,
                                     d1w, d1b, d2w, d2b, g2w, g2b,
                                     fc2w, fc2b, outRes, outAttn);
}

// round 7
// speedup vs baseline: 1.7271x; 1.7271x over previous
#include <cuda_runtime.h>
#include <cstdint>

#define Mm 32768   // B*N points

// ---------------- static device scratch ----------------
__device__ float g_qg[Mm * 64];   // x @ (wq@g1)
__device__ float g_kg[Mm * 64];   // x @ (wk@g1)
__device__ float g_v [Mm * 64];   // x @ wv
__device__ float g_Wd2g1[4096];   // d2 @ g1
__device__ float g_Wqg1[4096];    // wq @ g1
__device__ float g_Wkg1[4096];    // wk @ g1
__device__ float g_cvec[64];      // d2b @ g1 + g1b

// ---------------- f32x2 packed-FMA helpers ----------------
__device__ __forceinline__ unsigned long long pack2(float x, float y) {
    unsigned long long r; asm("mov.b64 %0, {%1, %2};" : "=l"(r) : "f"(x), "f"(y)); return r;
}
__device__ __forceinline__ void fma2(unsigned long long& d, unsigned long long a, unsigned long long b) {
    asm("fma.rn.f32x2 %0, %1, %2, %0;" : "+l"(d) : "l"(a), "l"(b));
}
__device__ __forceinline__ float2 unpk(unsigned long long v) {
    float x, y; asm("mov.b64 {%0, %1}, %2;" : "=f"(x), "=f"(y) : "l"(v)); return make_float2(x, y);
}

// ---------------- 4x4-tile gemm (k0/k1) ----------------
__device__ __forceinline__ void rank1(float a0, float a1, float a2, float a3,
                                      ulonglong2 b, unsigned long long acc[4][2]) {
    unsigned long long t;
    t = pack2(a0, a0); fma2(acc[0][0], t, b.x); fma2(acc[0][1], t, b.y);
    t = pack2(a1, a1); fma2(acc[1][0], t, b.x); fma2(acc[1][1], t, b.y);
    t = pack2(a2, a2); fma2(acc[2][0], t, b.x); fma2(acc[2][1], t, b.y);
    t = pack2(a3, a3); fma2(acc[3][0], t, b.x); fma2(acc[3][1], t, b.y);
}
__device__ __forceinline__ void gemm64(const float* As, const float* Ws,
                                       int r0, int c0, unsigned long long acc[4][2]) {
#pragma unroll
    for (int i = 0; i < 4; i++) { acc[i][0] = 0ULL; acc[i][1] = 0ULL; }
#pragma unroll
    for (int k4 = 0; k4 < 16; ++k4) {
        float4 a0 = *reinterpret_cast<const float4*>(As + (r0 + 0) * 68 + k4 * 4);
        float4 a1 = *reinterpret_cast<const float4*>(As + (r0 + 1) * 68 + k4 * 4);
        float4 a2 = *reinterpret_cast<const float4*>(As + (r0 + 2) * 68 + k4 * 4);
        float4 a3 = *reinterpret_cast<const float4*>(As + (r0 + 3) * 68 + k4 * 4);
        ulonglong2 b0 = *reinterpret_cast<const ulonglong2*>(Ws + (k4 * 4 + 0) * 68 + c0);
        ulonglong2 b1 = *reinterpret_cast<const ulonglong2*>(Ws + (k4 * 4 + 1) * 68 + c0);
        ulonglong2 b2 = *reinterpret_cast<const ulonglong2*>(Ws + (k4 * 4 + 2) * 68 + c0);
        ulonglong2 b3 = *reinterpret_cast<const ulonglong2*>(Ws + (k4 * 4 + 3) * 68 + c0);
        rank1(a0.x, a1.x, a2.x, a3.x, b0, acc);
        rank1(a0.y, a1.y, a2.y, a3.y, b1, acc);
        rank1(a0.z, a1.z, a2.z, a3.z, b2, acc);
        rank1(a0.w, a1.w, a2.w, a3.w, b3, acc);
    }
}
__device__ __forceinline__ void loadW(float* dst, const float* __restrict__ src, int tid) {
#pragma unroll
    for (int e = tid; e < 1024; e += 256) {
        int row = e >> 4, c4 = e & 15;
        float4 v = *reinterpret_cast<const float4*>(src + row * 64 + c4 * 4);
        *reinterpret_cast<float4*>(dst + row * 68 + c4 * 4) = v;
    }
}

// =========================================================================
// k0: weight products (canary kernel — keep identical across rounds)
// =========================================================================
__global__ __launch_bounds__(256)
void k0_prep(const float* __restrict__ d2w, const float* __restrict__ g1w,
             const float* __restrict__ wq, const float* __restrict__ wk,
             const float* __restrict__ d2b, const float* __restrict__ g1b) {
    __shared__ float As[64 * 68];
    __shared__ float Bs[64 * 68];
    const int tid = threadIdx.x, m = blockIdx.x;
    const float* A = (m == 0) ? d2w : (m == 1) ? wq : wk;
    loadW(As, A, tid);
    loadW(Bs, g1w, tid);
    __syncthreads();
    const int r0 = (tid >> 4) * 4, c0 = (tid & 15) * 4;
    unsigned long long acc[4][2];
    gemm64(As, Bs, r0, c0, acc);
    float* dst = (m == 0) ? g_Wd2g1 : (m == 1) ? g_Wqg1 : g_Wkg1;
#pragma unroll
    for (int i = 0; i < 4; i++) {
        float2 u0 = unpk(acc[i][0]), u1 = unpk(acc[i][1]);
        *reinterpret_cast<float4*>(dst + (r0 + i) * 64 + c0) = make_float4(u0.x, u0.y, u1.x, u1.y);
    }
    if (m == 0 && tid < 64) {
        float c = g1b[tid];
#pragma unroll 8
        for (int k = 0; k < 64; k++) c = fmaf(__ldg(&d2b[k]), Bs[k * 68 + tid], c);
        g_cvec[tid] = c;
    }
}

// =========================================================================
// k1: x = features@fc1+b ; qg = x@Wqg1 ; kg = x@Wkg1 ; v = x@wv
// =========================================================================
__global__ __launch_bounds__(256)
void k1_proj(const float* __restrict__ features,
             const float* __restrict__ fc1w, const float* __restrict__ fc1b,
             const float* __restrict__ wv) {
    __shared__ float Fs[64 * 68];
    __shared__ float Ws[64 * 68];
    const int tid = threadIdx.x;
    const int m0 = blockIdx.x * 64;
    const int r0 = (tid >> 4) * 4, c0 = (tid & 15) * 4;

#pragma unroll
    for (int e = tid; e < 1024; e += 256) {
        int row = e >> 4, c4 = e & 15;
        float4 v = *reinterpret_cast<const float4*>(features + (m0 + row) * 64 + c4 * 4);
        *reinterpret_cast<float4*>(Fs + row * 68 + c4 * 4) = v;
    }
    loadW(Ws, fc1w, tid);
    __syncthreads();

    unsigned long long acc[4][2];
    gemm64(Fs, Ws, r0, c0, acc);
    __syncthreads();
#pragma unroll
    for (int i = 0; i < 4; i++) {
        float2 u0 = unpk(acc[i][0]), u1 = unpk(acc[i][1]);
        Fs[(r0 + i) * 68 + c0 + 0] = u0.x + __ldg(&fc1b[c0 + 0]);
        Fs[(r0 + i) * 68 + c0 + 1] = u0.y + __ldg(&fc1b[c0 + 1]);
        Fs[(r0 + i) * 68 + c0 + 2] = u1.x + __ldg(&fc1b[c0 + 2]);
        Fs[(r0 + i) * 68 + c0 + 3] = u1.y + __ldg(&fc1b[c0 + 3]);
    }
    loadW(Ws, (const float*)g_Wqg1, tid);
    __syncthreads();
    gemm64(Fs, Ws, r0, c0, acc);
#pragma unroll
    for (int i = 0; i < 4; i++) {
        float2 u0 = unpk(acc[i][0]), u1 = unpk(acc[i][1]);
        *reinterpret_cast<float4*>(g_qg + (m0 + r0 + i) * 64 + c0) = make_float4(u0.x, u0.y, u1.x, u1.y);
    }
    __syncthreads();
    loadW(Ws, (const float*)g_Wkg1, tid);
    __syncthreads();
    gemm64(Fs, Ws, r0, c0, acc);
#pragma unroll
    for (int i = 0; i < 4; i++) {
        float2 u0 = unpk(acc[i][0]), u1 = unpk(acc[i][1]);
        *reinterpret_cast<float4*>(g_kg + (m0 + r0 + i) * 64 + c0) = make_float4(u0.x, u0.y, u1.x, u1.y);
    }
    __syncthreads();
    loadW(Ws, wv, tid);
    __syncthreads();
    gemm64(Fs, Ws, r0, c0, acc);
#pragma unroll
    for (int i = 0; i < 4; i++) {
        float2 u0 = unpk(acc[i][0]), u1 = unpk(acc[i][1]);
        *reinterpret_cast<float4*>(g_v + (m0 + r0 + i) * 64 + c0) = make_float4(u0.x, u0.y, u1.x, u1.y);
    }
}

// =========================================================================
// k2: 128 thr = 2 groups x 64 thr; group = 64 rows (4 pts x 16 nbrs).
// ONE resident weight buffer streamed d2 -> d2@g1 -> g2  => 93KB smem
// => 2 CTAs/SM, setup/epilogue overlapped by sibling CTA.
// =========================================================================
__device__ __forceinline__ void gemmT(const float* __restrict__ Tb,
                                      const float* __restrict__ W,
                                      int tr, int tcoff, unsigned long long acc[8][4]) {
    const float4* ap0 = reinterpret_cast<const float4*>(Tb + (tr +  0) * 68);
    const float4* ap1 = reinterpret_cast<const float4*>(Tb + (tr +  8) * 68);
    const float4* ap2 = reinterpret_cast<const float4*>(Tb + (tr + 16) * 68);
    const float4* ap3 = reinterpret_cast<const float4*>(Tb + (tr + 24) * 68);
    const float4* ap4 = reinterpret_cast<const float4*>(Tb + (tr + 32) * 68);
    const float4* ap5 = reinterpret_cast<const float4*>(Tb + (tr + 40) * 68);
    const float4* ap6 = reinterpret_cast<const float4*>(Tb + (tr + 48) * 68);
    const float4* ap7 = reinterpret_cast<const float4*>(Tb + (tr + 56) * 68);
    const ulonglong2* wp = reinterpret_cast<const ulonglong2*>(W + tcoff);
#pragma unroll
    for (int i = 0; i < 8; i++) { acc[i][0] = acc[i][1] = acc[i][2] = acc[i][3] = 0ULL; }
#pragma unroll
    for (int k4 = 0; k4 < 16; k4++) {
        float4 Av[8];
        Av[0] = ap0[k4]; Av[1] = ap1[k4]; Av[2] = ap2[k4]; Av[3] = ap3[k4];
        Av[4] = ap4[k4]; Av[5] = ap5[k4]; Av[6] = ap6[k4]; Av[7] = ap7[k4];
#pragma unroll
        for (int kk = 0; kk < 4; kk++) {
            ulonglong2 b0 = wp[(k4 * 4 + kk) * 17];
            ulonglong2 b1 = wp[(k4 * 4 + kk) * 17 + 1];
#pragma unroll
            for (int i = 0; i < 8; i++) {
                float a = (kk == 0) ? Av[i].x : (kk == 1) ? Av[i].y : (kk == 2) ? Av[i].z : Av[i].w;
                unsigned long long t = pack2(a, a);
                fma2(acc[i][0], t, b0.x); fma2(acc[i][1], t, b0.y);
                fma2(acc[i][2], t, b1.x); fma2(acc[i][3], t, b1.y);
            }
        }
    }
}

// cooperative padded weight load (128 threads): col -> col + 4*(col>=32)
__device__ __forceinline__ void loadWp(float* dst, const float* __restrict__ src, int tid) {
#pragma unroll
    for (int e = tid; e < 1024; e += 128) {
        int row = e >> 4, c4 = e & 15;
        float4 v = __ldg(reinterpret_cast<const float4*>(src + row * 64 + c4 * 4));
        *reinterpret_cast<float4*>(dst + row * 68 + c4 * 4 + ((c4 >> 3) << 2)) = v;
    }
}

__global__ __launch_bounds__(128)
void k2_main(const float* __restrict__ xyz, const float* __restrict__ features,
             const int* __restrict__ knn,
             const float* __restrict__ d1w, const float* __restrict__ d1b,
             const float* __restrict__ d2w, const float* __restrict__ d2b,
             const float* __restrict__ g2w, const float* __restrict__ g2b,
             const float* __restrict__ fc2w, const float* __restrict__ fc2b,
             float* __restrict__ outRes, float* __restrict__ outAttn) {
    extern __shared__ float sm[];
    float* Wbuf  = sm;                     // 4352 (padded cols)
    const int tid = threadIdx.x;
    const int g = tid >> 6, l = tid & 63;
    const int tc = l & 7, tr = l >> 3;
    float* Tb    = sm + 4352  + g * 4352;  // [4352, 13056)
    float* vpS   = sm + 13056 + g * 4352;  // [13056, 21760) padded cols
    float* qgS   = sm + 21760;             // 512
    float* resS  = sm + 22272;             // 512
    int*   growsS = (int*)(sm + 22784);    // 128
    float* d1S   = sm + 22912;             // 192
    float* d1bS  = sm + 23104;
    float* d2bS  = sm + 23168;
    float* cvecS = sm + 23232;
    float* g2bS  = sm + 23296;             // end 23360 floats = 93440 B
    const int pbase = blockIdx.x * 8;

    // ---- setup ----
    loadWp(Wbuf, d2w, tid);
    for (int e = tid; e < 192; e += 128) d1S[e] = d1w[e];
    if (tid < 64) { d1bS[tid] = d1b[tid]; d2bS[tid] = d2b[tid]; cvecS[tid] = g_cvec[tid]; g2bS[tid] = g2b[tid]; }
    for (int e = tid; e < 512; e += 128) qgS[e] = g_qg[(pbase + (e >> 6)) * 64 + (e & 63)];

    const int pi_st = pbase + g * 4 + (l >> 4);
    const int grow_st = ((pi_st >> 13) << 13) | knn[pi_st * 16 + (l & 15)];
    growsS[tid] = grow_st;
    const float rx = xyz[pi_st * 3 + 0] - xyz[grow_st * 3 + 0];
    const float ry = xyz[pi_st * 3 + 1] - xyz[grow_st * 3 + 1];
    const float rz = xyz[pi_st * 3 + 2] - xyz[grow_st * 3 + 2];
    __syncthreads();

    // ---- stage T = relu(rel@d1 + d1b) ----
    {
        const int r = l;
#pragma unroll
        for (int c4 = 0; c4 < 16; c4++) {
            float v[4];
#pragma unroll
            for (int u = 0; u < 4; u++) {
                int f = c4 * 4 + u;
                v[u] = fmaxf(fmaf(rx, d1S[f], fmaf(ry, d1S[64 + f], fmaf(rz, d1S[128 + f], d1bS[f]))), 0.f);
            }
            *reinterpret_cast<float4*>(Tb + r * 68 + c4 * 4) = make_float4(v[0], v[1], v[2], v[3]);
        }
    }
    __syncthreads();

    const int tcoff = tc * 8 + ((tc >> 2) << 2);   // padded col offset
    const int c0 = tc * 8;
    unsigned long long acc[8][4];

    // ---- GEMM1: pos = T@d2 (+d2b); vp = v_gather + pos -> vpS (padded) ----
    gemmT(Tb, Wbuf, tr, tcoff, acc);
#pragma unroll
    for (int i = 0; i < 8; i++) {
        int r = tr + 8 * i;
        int grow = growsS[g * 64 + r];
        float4 v0 = __ldg(reinterpret_cast<const float4*>(g_v + (size_t)grow * 64 + c0));
        float4 v1 = __ldg(reinterpret_cast<const float4*>(g_v + (size_t)grow * 64 + c0 + 4));
        float2 pA = unpk(acc[i][0]), pB = unpk(acc[i][1]), pC = unpk(acc[i][2]), pD = unpk(acc[i][3]);
        float4 w0 = make_float4(v0.x + pA.x + d2bS[c0 + 0], v0.y + pA.y + d2bS[c0 + 1],
                                v0.z + pB.x + d2bS[c0 + 2], v0.w + pB.y + d2bS[c0 + 3]);
        float4 w1 = make_float4(v1.x + pC.x + d2bS[c0 + 4], v1.y + pC.y + d2bS[c0 + 5],
                                v1.z + pD.x + d2bS[c0 + 6], v1.w + pD.y + d2bS[c0 + 7]);
        *reinterpret_cast<float4*>(vpS + r * 68 + tcoff)     = w0;
        *reinterpret_cast<float4*>(vpS + r * 68 + tcoff + 4) = w1;
    }
    __syncthreads();                 // GEMM1 Wbuf reads done
    loadWp(Wbuf, (const float*)g_Wd2g1, tid);
    __syncthreads();

    // ---- GEMM2: Tg = T@(d2@g1); a1 = relu(Tg + qg - kg + cvec) ----
    gemmT(Tb, Wbuf, tr, tcoff, acc);
#pragma unroll
    for (int i = 0; i < 8; i++) {
        int r = tr + 8 * i;
        int grow = growsS[g * 64 + r];
        int lp = g * 4 + (r >> 4);
        float4 k0v = __ldg(reinterpret_cast<const float4*>(g_kg + (size_t)grow * 64 + c0));
        float4 k1v = __ldg(reinterpret_cast<const float4*>(g_kg + (size_t)grow * 64 + c0 + 4));
        float4 q0 = *reinterpret_cast<const float4*>(qgS + lp * 64 + c0);
        float4 q1 = *reinterpret_cast<const float4*>(qgS + lp * 64 + c0 + 4);
        float2 aA = unpk(acc[i][0]), aB = unpk(acc[i][1]), aC = unpk(acc[i][2]), aD = unpk(acc[i][3]);
        float a0 = fmaxf(aA.x + q0.x - k0v.x + cvecS[c0 + 0], 0.f);
        float a1 = fmaxf(aA.y + q0.y - k0v.y + cvecS[c0 + 1], 0.f);
        float a2 = fmaxf(aB.x + q0.z - k0v.z + cvecS[c0 + 2], 0.f);
        float a3 = fmaxf(aB.y + q0.w - k0v.w + cvecS[c0 + 3], 0.f);
        float a4 = fmaxf(aC.x + q1.x - k1v.x + cvecS[c0 + 4], 0.f);
        float a5 = fmaxf(aC.y + q1.y - k1v.y + cvecS[c0 + 5], 0.f);
        float a6 = fmaxf(aD.x + q1.z - k1v.z + cvecS[c0 + 6], 0.f);
        float a7 = fmaxf(aD.y + q1.w - k1v.w + cvecS[c0 + 7], 0.f);
        acc[i][0] = pack2(a0, a1); acc[i][1] = pack2(a2, a3);
        acc[i][2] = pack2(a4, a5); acc[i][3] = pack2(a6, a7);
    }
    __syncthreads();                 // GEMM2 Tb/Wbuf reads done
#pragma unroll
    for (int i = 0; i < 8; i++) {
        int r = tr + 8 * i;
        *reinterpret_cast<ulonglong2*>(Tb + r * 68 + c0)     = make_ulonglong2(acc[i][0], acc[i][1]);
        *reinterpret_cast<ulonglong2*>(Tb + r * 68 + c0 + 4) = make_ulonglong2(acc[i][2], acc[i][3]);
    }
    loadWp(Wbuf, g2w, tid);
    __syncthreads();

    // ---- GEMM3: logits = a1@g2 + g2b ----
    gemmT(Tb, Wbuf, tr, tcoff, acc);
#pragma unroll
    for (int i = 0; i < 8; i++) {
        float2 aA = unpk(acc[i][0]), aB = unpk(acc[i][1]), aC = unpk(acc[i][2]), aD = unpk(acc[i][3]);
        acc[i][0] = pack2(aA.x + g2bS[c0 + 0], aA.y + g2bS[c0 + 1]);
        acc[i][1] = pack2(aB.x + g2bS[c0 + 2], aB.y + g2bS[c0 + 3]);
        acc[i][2] = pack2(aC.x + g2bS[c0 + 4], aC.y + g2bS[c0 + 5]);
        acc[i][3] = pack2(aD.x + g2bS[c0 + 6], aD.y + g2bS[c0 + 7]);
    }
    __syncthreads();                 // GEMM3 reads done
#pragma unroll
    for (int i = 0; i < 8; i++) {
        int r = tr + 8 * i;
        *reinterpret_cast<ulonglong2*>(Tb + r * 68 + c0)     = make_ulonglong2(acc[i][0], acc[i][1]);
        *reinterpret_cast<ulonglong2*>(Tb + r * 68 + c0 + 4) = make_ulonglong2(acc[i][2], acc[i][3]);
    }
    __syncthreads();

    // ---- softmax over neighbors (axis j) per (point, channel) + res ----
    {
        const int f = l;
        const int fp = f + ((f >> 5) << 2);   // padded col for vpS
#pragma unroll
        for (int p = 0; p < 4; p++) {
            const int pi = pbase + g * 4 + p;
            float z[16], m = -3.402823e38f;
#pragma unroll
            for (int j = 0; j < 16; j++) {
                z[j] = Tb[(p * 16 + j) * 68 + f];
                m = fmaxf(m, z[j]);
            }
            float s = 0.f;
#pragma unroll
            for (int j = 0; j < 16; j++) { float e = __expf((z[j] - m) * 0.125f); z[j] = e; s += e; }
            float inv = 1.f / s, racc = 0.f;
#pragma unroll
            for (int j = 0; j < 16; j++) {
                float a = z[j] * inv;
                outAttn[((size_t)pi * 16 + j) * 64 + f] = a;
                racc = fmaf(a, vpS[(p * 16 + j) * 68 + fp], racc);
            }
            resS[(g * 4 + p) * 64 + f] = racc;
        }
    }
    __syncthreads();

    // ---- out = res@fc2 + fc2b + features ----
    {
        const int f = l, lpb = g * 4;
        float o0 = fc2b[f] + features[(size_t)(pbase + lpb + 0) * 64 + f];
        float o1 = fc2b[f] + features[(size_t)(pbase + lpb + 1) * 64 + f];
        float o2 = fc2b[f] + features[(size_t)(pbase + lpb + 2) * 64 + f];
        float o3 = fc2b[f] + features[(size_t)(pbase + lpb + 3) * 64 + f];
#pragma unroll 8
        for (int i = 0; i < 64; i++) {
            float w = __ldg(fc2w + i * 64 + f);
            o0 = fmaf(resS[(lpb + 0) * 64 + i], w, o0);
            o1 = fmaf(resS[(lpb + 1) * 64 + i], w, o1);
            o2 = fmaf(resS[(lpb + 2) * 64 + i], w, o2);
            o3 = fmaf(resS[(lpb + 3) * 64 + i], w, o3);
        }
        outRes[(size_t)(pbase + lpb + 0) * 64 + f] = o0;
        outRes[(size_t)(pbase + lpb + 1) * 64 + f] = o1;
        outRes[(size_t)(pbase + lpb + 2) * 64 + f] = o2;
        outRes[(size_t)(pbase + lpb + 3) * 64 + f] = o3;
    }
}

// =========================================================================
extern "C" void kernel_launch(void* const* d_in, const int* in_sizes, int n_in,
                              void* d_out, int out_size) {
    const float* xyz      = (const float*)d_in[0];
    const float* features = (const float*)d_in[1];
    const int*   knn      = (const int*)d_in[2];
    const float* fc1w = (const float*)d_in[3];
    const float* fc1b = (const float*)d_in[4];
    const float* fc2w = (const float*)d_in[5];
    const float* fc2b = (const float*)d_in[6];
    const float* d1w  = (const float*)d_in[7];
    const float* d1b  = (const float*)d_in[8];
    const float* d2w  = (const float*)d_in[9];
    const float* d2b  = (const float*)d_in[10];
    const float* g1w  = (const float*)d_in[11];
    const float* g1b  = (const float*)d_in[12];
    const float* g2w  = (const float*)d_in[13];
    const float* g2b  = (const float*)d_in[14];
    const float* wq   = (const float*)d_in[15];
    const float* wk   = (const float*)d_in[16];
    const float* wv   = (const float*)d_in[17];

    float* outRes  = (float*)d_out;
    float* outAttn = outRes + (size_t)Mm * 64;   // tuple order: (res, attn)

    const int smem2 = 23360 * 4;   // 93440 B -> 2 CTAs/SM
    cudaFuncSetAttribute(k2_main, cudaFuncAttributeMaxDynamicSharedMemorySize, smem2);

    k0_prep<<<3, 256>>>(d2w, g1w, wq, wk, d2b, g1b);
    k1_proj<<<Mm / 64, 256>>>(features, fc1w, fc1b, wv);
    k2_main<<<Mm / 8, 128, smem2>>>(xyz, features, knn,
                                    d1w, d1b, d2w, d2b, g2w, g2b,
                                    fc2w, fc2b, outRes, outAttn);
}